// round 17
// baseline (speedup 1.0000x reference)
#include <cuda_runtime.h>
#include <cuda_bf16.h>
#include <math.h>

// ---------------------------------------------------------------------------
// Problem constants
// ---------------------------------------------------------------------------
#define LAYERS 4
#define NH     16
#define DM     1024
#define VO     32000
#define TT     2048
#define BBATCH 2
#define HDIM   64
#define BTOK   (BBATCH*TT)   // 4096

// weight-plane offsets (elements)
#define QW_SZ  ((size_t)LAYERS*3*DM*DM)
#define PW_SZ  ((size_t)LAYERS*DM*DM)
#define F1_SZ  ((size_t)LAYERS*4*DM*DM)
#define F2_SZ  ((size_t)LAYERS*4*DM*DM)
#define TK_SZ  ((size_t)VO*DM)
#define QW_OFF ((size_t)0)
#define PW_OFF (QW_OFF+QW_SZ)
#define F1_OFF (PW_OFF+PW_SZ)
#define F2_OFF (F1_OFF+F1_SZ)
#define TK_OFF (F2_OFF+F2_SZ)
#define W_TOTAL (TK_OFF+TK_SZ)

// ---------------------------------------------------------------------------
// Scratch (static __device__ arrays: the sanctioned no-alloc path)
// ---------------------------------------------------------------------------
__device__ float g_x [(size_t)BTOK * DM];

__device__ __nv_bfloat16 g_h_hi  [(size_t)BTOK * DM];
__device__ __nv_bfloat16 g_h_lo  [(size_t)BTOK * DM];
__device__ __nv_bfloat16 g_qkv_hi[(size_t)BTOK * 3 * DM];
__device__ __nv_bfloat16 g_qkv_lo[(size_t)BTOK * 3 * DM];
__device__ __nv_bfloat16 g_at_hi [(size_t)BTOK * DM];
__device__ __nv_bfloat16 g_at_lo [(size_t)BTOK * DM];
__device__ __nv_bfloat16 g_mid_hi[(size_t)BTOK * 4 * DM];
__device__ __nv_bfloat16 g_mid_lo[(size_t)BTOK * 4 * DM];
__device__ __nv_bfloat16 g_w_hi  [W_TOTAL];
__device__ __nv_bfloat16 g_w_lo  [W_TOTAL];

// ---------------------------------------------------------------------------
// Small helpers
// ---------------------------------------------------------------------------
__device__ __forceinline__ float gelu_exact(float x) {
    return 0.5f * x * (1.0f + erff(x * 0.70710678118654752440f));
}
__device__ __forceinline__ void split1(float v, __nv_bfloat16& h, __nv_bfloat16& l) {
    h = __float2bfloat16(v);
    l = __float2bfloat16(v - __bfloat162float(h));
}
// split fp32 pair into packed bf16x2 hi & lo words
__device__ __forceinline__ void split_pack2(float x, float y, unsigned& h, unsigned& l) {
    __nv_bfloat16 xh, xl, yh, yl;
    split1(x, xh, xl); split1(y, yh, yl);
    __nv_bfloat162 hh = __halves2bfloat162(xh, yh);
    __nv_bfloat162 ll = __halves2bfloat162(xl, yl);
    h = *reinterpret_cast<unsigned*>(&hh);
    l = *reinterpret_cast<unsigned*>(&ll);
}

template <bool DOMAX>
__device__ __forceinline__ float block_reduce(float v) {
    __shared__ float sh[33];
    const int lane = threadIdx.x & 31;
    const int wid  = threadIdx.x >> 5;
#pragma unroll
    for (int o = 16; o; o >>= 1) {
        float t = __shfl_xor_sync(0xffffffffu, v, o);
        v = DOMAX ? fmaxf(v, t) : (v + t);
    }
    if (lane == 0) sh[wid] = v;
    __syncthreads();
    const int nw = blockDim.x >> 5;
    if (wid == 0) {
        float t = (lane < nw) ? sh[lane] : (DOMAX ? -3.4e38f : 0.0f);
#pragma unroll
        for (int o = 16; o; o >>= 1) {
            float u = __shfl_xor_sync(0xffffffffu, t, o);
            t = DOMAX ? fmaxf(t, u) : (t + u);
        }
        if (lane == 0) sh[32] = t;
    }
    __syncthreads();
    float r = sh[32];
    __syncthreads();
    return r;
}

__device__ __forceinline__ void mma16816(float* c, const unsigned* a, const unsigned* b) {
    asm volatile(
        "mma.sync.aligned.m16n8k16.row.col.f32.bf16.bf16.f32 "
        "{%0,%1,%2,%3}, {%4,%5,%6,%7}, {%8,%9}, {%0,%1,%2,%3};\n"
        : "+f"(c[0]), "+f"(c[1]), "+f"(c[2]), "+f"(c[3])
        : "r"(a[0]), "r"(a[1]), "r"(a[2]), "r"(a[3]), "r"(b[0]), "r"(b[1]));
}
__device__ __forceinline__ void ldsm4(unsigned* r, unsigned a) {
    asm volatile("ldmatrix.sync.aligned.m8n8.x4.shared.b16 {%0,%1,%2,%3}, [%4];"
                 : "=r"(r[0]), "=r"(r[1]), "=r"(r[2]), "=r"(r[3]) : "r"(a));
}
__device__ __forceinline__ void ldsm4t(unsigned* r, unsigned a) {
    asm volatile("ldmatrix.sync.aligned.m8n8.x4.trans.shared.b16 {%0,%1,%2,%3}, [%4];"
                 : "=r"(r[0]), "=r"(r[1]), "=r"(r[2]), "=r"(r[3]) : "r"(a));
}
__device__ __forceinline__ void cp16(unsigned saddr, const void* g) {
    asm volatile("cp.async.cg.shared.global [%0], [%1], 16;" :: "r"(saddr), "l"(g));
}
__device__ __forceinline__ void cp_commit() { asm volatile("cp.async.commit_group;"); }
template <int N>
__device__ __forceinline__ void cp_wait() { asm volatile("cp.async.wait_group %0;" :: "n"(N)); }

// ---------------------------------------------------------------------------
// fp32 -> bf16 hi/lo split (weights)
// ---------------------------------------------------------------------------
__global__ void split_k(const float* __restrict__ s,
                        __nv_bfloat16* __restrict__ hi,
                        __nv_bfloat16* __restrict__ lo, long n4) {
    long i = (long)blockIdx.x * blockDim.x + threadIdx.x;
    const long stride = (long)gridDim.x * blockDim.x;
    for (; i < n4; i += stride) {
        float4 v = ((const float4*)s)[i];
        unsigned h0, l0, h1, l1;
        split_pack2(v.x, v.y, h0, l0);
        split_pack2(v.z, v.w, h1, l1);
        ((unsigned*)hi)[2*i+0] = h0;
        ((unsigned*)hi)[2*i+1] = h1;
        ((unsigned*)lo)[2*i+0] = l0;
        ((unsigned*)lo)[2*i+1] = l1;
    }
}

// ---------------------------------------------------------------------------
// Embedding (fp32 residual)
// ---------------------------------------------------------------------------
__global__ void embed_k(const int* __restrict__ ids,
                        const float* __restrict__ tok,
                        const float* __restrict__ pos,
                        const float* __restrict__ ctx,
                        float* __restrict__ x) {
    const int bt = blockIdx.x;
    const int b  = bt / TT;
    const int t  = bt - b * TT;
    const int id = ids[bt];
    const int d  = threadIdx.x * 4;
    const float4 a = *(const float4*)(tok + (size_t)id * DM + d);
    const float4 p = *(const float4*)(pos + (size_t)t  * DM + d);
    const float4 c = *(const float4*)(ctx + (size_t)b  * DM + d);
    float4 r;
    r.x = a.x + p.x + c.x; r.y = a.y + p.y + c.y;
    r.z = a.z + p.z + c.z; r.w = a.w + p.w + c.w;
    *(float4*)(x + (size_t)bt * DM + d) = r;
}

// ---------------------------------------------------------------------------
// LayerNorm: fp32 in -> bf16 hi/lo planes out
// ---------------------------------------------------------------------------
__global__ void layernorm_split_k(const float* __restrict__ xin,
                                  __nv_bfloat16* __restrict__ yhi,
                                  __nv_bfloat16* __restrict__ ylo,
                                  const float* __restrict__ w,
                                  const float* __restrict__ b) {
    const size_t row = blockIdx.x;
    const float* xr = xin + row * DM;
    const int d = threadIdx.x * 4;

    const float4 v = *(const float4*)(xr + d);
    float s  = v.x + v.y + v.z + v.w;
    float s2 = v.x*v.x + v.y*v.y + v.z*v.z + v.w*v.w;
    s  = block_reduce<false>(s);
    s2 = block_reduce<false>(s2);
    const float mean = s * (1.0f / DM);
    const float var  = s2 * (1.0f / DM) - mean * mean;
    const float rstd = rsqrtf(var + 1e-5f);

    const float4 ww = *(const float4*)(w + d);
    const float4 bb = *(const float4*)(b + d);
    float o0 = (v.x - mean) * rstd * ww.x + bb.x;
    float o1 = (v.y - mean) * rstd * ww.y + bb.y;
    float o2 = (v.z - mean) * rstd * ww.z + bb.z;
    float o3 = (v.w - mean) * rstd * ww.w + bb.w;
    unsigned h0, l0, h1, l1;
    split_pack2(o0, o1, h0, l0);
    split_pack2(o2, o3, h1, l1);
    unsigned* ph = (unsigned*)(yhi + row * DM + d);
    unsigned* pl = (unsigned*)(ylo + row * DM + d);
    ph[0] = h0; ph[1] = h1;
    pl[0] = l0; pl[1] = l1;
}

// ---------------------------------------------------------------------------
// Flash attention (causal), bf16x3 precision, online fp32 softmax.
// grid = (T/128, B*NH); 256 threads = 8 warps, warp w owns Q rows
// m0 + 16w .. +15.  K/V blocks of 128 tokens streamed through a 3-stage
// cp.async ring (Khi|Klo|Vhi|Vlo, 16KB each, XOR-swizzled 128B rows).
// S fragments stay in registers; P packs directly into mma A-fragments.
// MMA terms issued in 3 passes over independent accumulators (reuse
// distance 4) to avoid accumulator-RAW serialization.
// ---------------------------------------------------------------------------
__global__ __launch_bounds__(256, 1)
void fattn_k(const __nv_bfloat16* __restrict__ QKVhi,
             const __nv_bfloat16* __restrict__ QKVlo,
             __nv_bfloat16* __restrict__ Ohi,
             __nv_bfloat16* __restrict__ Olo,
             float scale) {
    constexpr int PL  = 128 * 128;   // one plane: 128 rows x 128B
    constexpr int STG = 4 * PL;      // 64 KB per stage

    extern __shared__ char smem[];
    const unsigned sb = (unsigned)__cvta_generic_to_shared(smem);

    const int z  = blockIdx.y;
    const int bb = z / NH;
    const int hh = z - bb * NH;
    const int qb = (int)gridDim.x - 1 - (int)blockIdx.x;   // heavy tiles first
    const int m0 = qb * 128;

    const int tid  = threadIdx.x;
    const int warp = tid >> 5;
    const int lane = tid & 31;
    const int g    = lane >> 3;
    const int l8   = lane & 7;
    const int qr   = lane >> 2;          // row-in-tile (0..7)
    const int qc   = (lane & 3) * 2;     // col pair base

    const size_t rowbase = (size_t)bb * TT;
    const size_t hoff    = (size_t)hh * HDIM;

    // ---- Q fragments: direct LDG from split planes (A-frag layout) ----
    unsigned qf[2][4][4];   // [plane][k16-chunk][reg]
    {
        const int r0 = m0 + warp * 16 + qr;
        const size_t a0 = (rowbase + r0) * (size_t)(3 * DM) + hoff;
        const size_t a1 = a0 + (size_t)8 * (3 * DM);
#pragma unroll
        for (int p = 0; p < 2; p++) {
            const __nv_bfloat16* src = p ? QKVlo : QKVhi;
#pragma unroll
            for (int c = 0; c < 4; c++) {
                const int k = c * 16 + qc;
                qf[p][c][0] = *(const unsigned*)(src + a0 + k);
                qf[p][c][1] = *(const unsigned*)(src + a1 + k);
                qf[p][c][2] = *(const unsigned*)(src + a0 + k + 8);
                qf[p][c][3] = *(const unsigned*)(src + a1 + k + 8);
            }
        }
    }

    float oacc[8][4];
#pragma unroll
    for (int t = 0; t < 8; t++)
#pragma unroll
        for (int e = 0; e < 4; e++) oacc[t][e] = 0.0f;
    float m0r = -1e30f, m1r = -1e30f;    // running max (rows r0 / r1)
    float l0r = 0.0f,   l1r = 0.0f;      // running sum

    // ---- K/V block staging ----
    auto issueKV = [&](int kb) {
        const unsigned so = sb + (unsigned)((kb % 3) * STG);
        const size_t tok0 = rowbase + (size_t)kb * 128;
#pragma unroll
        for (int i = 0; i < 8; i++) {     // K planes
            const int q  = tid + (i << 8);
            const int pl = q >> 10;
            const int r  = (q >> 3) & 127;
            const int c  = q & 7;
            const __nv_bfloat16* gp =
                (pl ? QKVlo : QKVhi) + (tok0 + r) * (size_t)(3 * DM) + DM + hoff + c * 8;
            cp16(so + (unsigned)(pl * PL + r * 128 + ((c ^ (r & 7)) << 4)), gp);
        }
#pragma unroll
        for (int i = 0; i < 8; i++) {     // V planes
            const int q  = tid + (i << 8);
            const int pl = q >> 10;
            const int r  = (q >> 3) & 127;
            const int c  = q & 7;
            const __nv_bfloat16* gp =
                (pl ? QKVlo : QKVhi) + (tok0 + r) * (size_t)(3 * DM) + 2 * DM + hoff + c * 8;
            cp16(so + (unsigned)(2 * PL + pl * PL + r * 128 + ((c ^ (r & 7)) << 4)), gp);
        }
    };

    issueKV(0); cp_commit();
    if (qb >= 1) issueKV(1);
    cp_commit();

    const int gr0 = m0 + warp * 16 + qr;
    const int gr1 = gr0 + 8;

    for (int kb = 0; kb <= qb; kb++) {
        if (kb < qb) cp_wait<1>(); else cp_wait<0>();
        __syncthreads();                       // all warps past previous compute

        const unsigned sK = sb + (unsigned)((kb % 3) * STG);
        const unsigned sV = sK + 2 * PL;

        // ---- S = scale * Q @ K^T (16 n-tiles of 8 cols) ----
        float sacc[16][4];
#pragma unroll
        for (int t = 0; t < 16; t++)
#pragma unroll
            for (int e = 0; e < 4; e++) sacc[t][e] = 0.0f;

#pragma unroll
        for (int s = 0; s < 4; s++) {
#pragma unroll
            for (int jq = 0; jq < 4; jq++) {       // pairs of 16-col groups
                unsigned bh[2][4], bl[2][4];
#pragma unroll
                for (int u = 0; u < 2; u++) {
                    const int n  = 16 * (2*jq + u) + (g >> 1) * 8 + l8;
                    const int ch = 2 * s + (g & 1);
                    const unsigned off = (unsigned)(n * 128 + ((ch ^ (n & 7)) << 4));
                    ldsm4(bh[u], sK + off);
                    ldsm4(bl[u], sK + PL + off);
                }
                // pass 1: hi*hi
#pragma unroll
                for (int u = 0; u < 2; u++) {
                    mma16816(sacc[4*jq + 2*u],     qf[0][s], bh[u]);
                    mma16816(sacc[4*jq + 2*u + 1], qf[0][s], bh[u] + 2);
                }
                // stage prefetch under the MMA shadow (once per KV block)
                if (s == 0 && jq == 0) {
                    if (kb + 2 <= qb) issueKV(kb + 2);
                    cp_commit();
                }
                // pass 2: hi*lo
#pragma unroll
                for (int u = 0; u < 2; u++) {
                    mma16816(sacc[4*jq + 2*u],     qf[0][s], bl[u]);
                    mma16816(sacc[4*jq + 2*u + 1], qf[0][s], bl[u] + 2);
                }
                // pass 3: lo*hi
#pragma unroll
                for (int u = 0; u < 2; u++) {
                    mma16816(sacc[4*jq + 2*u],     qf[1][s], bh[u]);
                    mma16816(sacc[4*jq + 2*u + 1], qf[1][s], bh[u] + 2);
                }
            }
        }

        // ---- scale, causal mask, online softmax ----
        float mx0 = -1e30f, mx1 = -1e30f;
        const bool diag = (kb == qb);
#pragma unroll
        for (int t = 0; t < 16; t++) {
            sacc[t][0] *= scale; sacc[t][1] *= scale;
            sacc[t][2] *= scale; sacc[t][3] *= scale;
            if (diag) {
                const int cb = kb * 128 + 8 * t + qc;
                if (cb     > gr0) sacc[t][0] = -1e30f;
                if (cb + 1 > gr0) sacc[t][1] = -1e30f;
                if (cb     > gr1) sacc[t][2] = -1e30f;
                if (cb + 1 > gr1) sacc[t][3] = -1e30f;
            }
            mx0 = fmaxf(mx0, fmaxf(sacc[t][0], sacc[t][1]));
            mx1 = fmaxf(mx1, fmaxf(sacc[t][2], sacc[t][3]));
        }
        mx0 = fmaxf(mx0, __shfl_xor_sync(0xffffffffu, mx0, 1));
        mx0 = fmaxf(mx0, __shfl_xor_sync(0xffffffffu, mx0, 2));
        mx1 = fmaxf(mx1, __shfl_xor_sync(0xffffffffu, mx1, 1));
        mx1 = fmaxf(mx1, __shfl_xor_sync(0xffffffffu, mx1, 2));

        const float mn0 = fmaxf(m0r, mx0);
        const float mn1 = fmaxf(m1r, mx1);
        const float sc0 = __expf(m0r - mn0);
        const float sc1 = __expf(m1r - mn1);
        m0r = mn0; m1r = mn1;

#pragma unroll
        for (int t = 0; t < 8; t++) {
            oacc[t][0] *= sc0; oacc[t][1] *= sc0;
            oacc[t][2] *= sc1; oacc[t][3] *= sc1;
        }

        float sum0 = 0.0f, sum1 = 0.0f;
#pragma unroll
        for (int t = 0; t < 16; t++) {
            sacc[t][0] = __expf(sacc[t][0] - mn0);
            sacc[t][1] = __expf(sacc[t][1] - mn0);
            sacc[t][2] = __expf(sacc[t][2] - mn1);
            sacc[t][3] = __expf(sacc[t][3] - mn1);
            sum0 += sacc[t][0] + sacc[t][1];
            sum1 += sacc[t][2] + sacc[t][3];
        }
        sum0 += __shfl_xor_sync(0xffffffffu, sum0, 1);
        sum0 += __shfl_xor_sync(0xffffffffu, sum0, 2);
        sum1 += __shfl_xor_sync(0xffffffffu, sum1, 1);
        sum1 += __shfl_xor_sync(0xffffffffu, sum1, 2);
        l0r = l0r * sc0 + sum0;
        l1r = l1r * sc1 + sum1;

        // ---- O += P @ V  (P packs straight into A fragments) ----
#pragma unroll
        for (int c = 0; c < 8; c++) {
            unsigned ph[4], pl_[4];
            split_pack2(sacc[2*c][0],   sacc[2*c][1],   ph[0], pl_[0]);
            split_pack2(sacc[2*c][2],   sacc[2*c][3],   ph[1], pl_[1]);
            split_pack2(sacc[2*c+1][0], sacc[2*c+1][1], ph[2], pl_[2]);
            split_pack2(sacc[2*c+1][2], sacc[2*c+1][3], ph[3], pl_[3]);
            const int klo = 16 * c + (g & 1) * 8 + l8;
#pragma unroll
            for (int jq = 0; jq < 2; jq++) {      // pairs of 16-col chunks
                unsigned vh[2][4], vl[2][4];
#pragma unroll
                for (int u = 0; u < 2; u++) {
                    const int ch = 2 * (2*jq + u) + (g >> 1);
                    const unsigned off = (unsigned)(klo * 128 + ((ch ^ (klo & 7)) << 4));
                    ldsm4t(vh[u], sV + off);
                    ldsm4t(vl[u], sV + PL + off);
                }
                // pass 1: hi*hi
#pragma unroll
                for (int u = 0; u < 2; u++) {
                    mma16816(oacc[4*jq + 2*u],     ph, vh[u]);
                    mma16816(oacc[4*jq + 2*u + 1], ph, vh[u] + 2);
                }
                // pass 2: hi*lo
#pragma unroll
                for (int u = 0; u < 2; u++) {
                    mma16816(oacc[4*jq + 2*u],     ph, vl[u]);
                    mma16816(oacc[4*jq + 2*u + 1], ph, vl[u] + 2);
                }
                // pass 3: lo*hi
#pragma unroll
                for (int u = 0; u < 2; u++) {
                    mma16816(oacc[4*jq + 2*u],     pl_, vh[u]);
                    mma16816(oacc[4*jq + 2*u + 1], pl_, vh[u] + 2);
                }
            }
        }
    }

    // ---- epilogue: O /= l, split, store ----
    const float inv0 = 1.0f / l0r;
    const float inv1 = 1.0f / l1r;
    const size_t o0 = (rowbase + gr0) * (size_t)DM + hoff;
    const size_t o1 = (rowbase + gr1) * (size_t)DM + hoff;
#pragma unroll
    for (int t = 0; t < 8; t++) {
        const int n = 8 * t + qc;
        unsigned h, l;
        split_pack2(oacc[t][0] * inv0, oacc[t][1] * inv0, h, l);
        *(unsigned*)(Ohi + o0 + n) = h;
        *(unsigned*)(Olo + o0 + n) = l;
        split_pack2(oacc[t][2] * inv1, oacc[t][3] * inv1, h, l);
        *(unsigned*)(Ohi + o1 + n) = h;
        *(unsigned*)(Olo + o1 + n) = l;
    }
}

// ---------------------------------------------------------------------------
// mma.sync GEMM, bf16x3 split emulation of fp32 (NT weights path).
//   C[m,n] = epi( scale * sum_k A[m,k] * B[n,k] ),  pre-split bf16 planes.
// BK=64, 3-stage cp.async ring, XOR-swizzled 128B rows, register
// double-buffered fragments, 8 warps (2m x 4n), warp tile 64x32.
// MMA terms issued in 3 passes over 16 independent accumulators.
//   OUT: 0 = fp32 C (+opt residual), 1 = split bf16 planes (+opt GELU)
// ---------------------------------------------------------------------------
template <int BM, int BN, int OUT, bool DOGELU>
__global__ __launch_bounds__(256, 1)
void tgemm_k(const __nv_bfloat16* __restrict__ Ahi, const __nv_bfloat16* __restrict__ Alo,
             long lda,
             const __nv_bfloat16* __restrict__ Bhi, const __nv_bfloat16* __restrict__ Blo,
             long ldb,
             float* __restrict__ C,
             __nv_bfloat16* __restrict__ Chi, __nv_bfloat16* __restrict__ Clo,
             long ldc,
             int K,
             const float* __restrict__ bias,
             const float* __restrict__ resid,
             float scale) {
    constexpr int MT   = 4;
    constexpr int NT   = BN / 8 / 4;
    constexpr int PLA  = 128 * 128;
    constexpr int PLB  = BN * 128;
    constexpr int SA   = 2 * PLA;
    constexpr int STAGE = SA + 2 * PLB;
    static_assert(BM == 128, "BM=128 assumed by staging");

    extern __shared__ char smem[];
    const unsigned sb = (unsigned)__cvta_generic_to_shared(smem);

    // tile raster: groups of 8 m-blocks for L2 reuse of B (gridDim.y % 8 == 0)
    const int gx  = gridDim.x;
    const int lin = blockIdx.y * gx + blockIdx.x;
    const int per = 8 * gx;
    const int m0 = ((lin / per) * 8 + (lin % 8)) * BM;
    const int n0 = ((lin % per) / 8) * BN;
    const int nIt = K / 64;

    const int tid  = threadIdx.x;
    const int warp = tid >> 5;
    const int lane = tid & 31;
    const int wm   = warp & 1;
    const int wn   = warp >> 1;
    const int l8   = lane & 7;
    const int g    = lane >> 3;

    float acc[MT][NT][4];
#pragma unroll
    for (int i = 0; i < MT; i++)
#pragma unroll
        for (int j = 0; j < NT; j++)
#pragma unroll
            for (int q = 0; q < 4; q++) acc[i][j][q] = 0.0f;

    auto issue = [&](int stg) {
        const unsigned so = sb + (unsigned)((stg % 3) * STAGE);
        const long kk = (long)stg * 64;
#pragma unroll
        for (int i = 0; i < 8; i++) {
            const int q  = tid + (i << 8);
            const int pl = q >> 10;
            const int r  = (q >> 3) & 127;
            const int c  = q & 7;
            const __nv_bfloat16* gp = (pl ? Alo : Ahi) + (size_t)(m0 + r) * lda + kk + c * 8;
            cp16(so + (unsigned)(pl * PLA + r * 128 + ((c ^ (r & 7)) << 4)), gp);
        }
#pragma unroll
        for (int i = 0; i < 8; i++) {
            const int q  = tid + (i << 8);
            const int pl = q >> 10;
            const int r  = (q >> 3) & 127;
            const int c  = q & 7;
            const __nv_bfloat16* gp = (pl ? Blo : Bhi) + (size_t)(n0 + r) * ldb + kk + c * 8;
            cp16(so + (unsigned)(SA + pl * PLB + r * 128 + ((c ^ (r & 7)) << 4)), gp);
        }
    };

    const int aRow = (g & 1) * 8 + l8;
    const int aCh  = g >> 1;

    auto loadA = [&](unsigned sA0, int s, unsigned a[MT][2][4]) {
#pragma unroll
        for (int i = 0; i < MT; i++) {
            const int m  = wm * 64 + i * 16 + aRow;
            const int ch = 2 * s + aCh;
            const unsigned off = (unsigned)(m * 128 + ((ch ^ (m & 7)) << 4));
            ldsm4(a[i][0], sA0 + off);
            ldsm4(a[i][1], sA0 + PLA + off);
        }
    };
    auto loadB = [&](unsigned sB0, int s, unsigned b[NT][2][2]) {
#pragma unroll
        for (int jp = 0; jp < NT / 2; jp++) {
            const int n  = wn * (NT * 8) + jp * 16 + (g >> 1) * 8 + l8;
            const int ch = 2 * s + (g & 1);
            const unsigned off = (unsigned)(n * 128 + ((ch ^ (n & 7)) << 4));
            unsigned t[4];
            ldsm4(t, sB0 + off);
            b[2*jp][0][0] = t[0]; b[2*jp][0][1] = t[1];
            b[2*jp+1][0][0] = t[2]; b[2*jp+1][0][1] = t[3];
            ldsm4(t, sB0 + PLB + off);
            b[2*jp][1][0] = t[0]; b[2*jp][1][1] = t[1];
            b[2*jp+1][1][0] = t[2]; b[2*jp+1][1][1] = t[3];
        }
    };

    issue(0); cp_commit();
    if (nIt > 1) issue(1);
    cp_commit();

    for (int it = 0; it < nIt; it++) {
        if (it + 1 < nIt) cp_wait<1>(); else cp_wait<0>();
        __syncthreads();

        const unsigned sA0 = sb + (unsigned)((it % 3) * STAGE);
        const unsigned sB0 = sA0 + SA;

        unsigned ra[2][MT][2][4];
        unsigned rb[2][NT][2][2];
        loadA(sA0, 0, ra[0]);
        loadB(sB0, 0, rb[0]);
#pragma unroll
        for (int s = 0; s < 4; s++) {
            const int cur = s & 1;
            if (s < 3) {
                loadA(sA0, s + 1, ra[cur ^ 1]);
                loadB(sB0, s + 1, rb[cur ^ 1]);
            }
            // pass 1: hi*hi  (16 independent accumulators)
#pragma unroll
            for (int i = 0; i < MT; i++)
#pragma unroll
                for (int j = 0; j < NT; j++)
                    mma16816(acc[i][j], ra[cur][i][0], rb[cur][j][0]);
            // stage prefetch under the MMA shadow (once per iteration)
            if (s == 0) {
                if (it + 2 < nIt) issue(it + 2);
                cp_commit();
            }
            // pass 2: hi*lo
#pragma unroll
            for (int i = 0; i < MT; i++)
#pragma unroll
                for (int j = 0; j < NT; j++)
                    mma16816(acc[i][j], ra[cur][i][0], rb[cur][j][1]);
            // pass 3: lo*hi
#pragma unroll
            for (int i = 0; i < MT; i++)
#pragma unroll
                for (int j = 0; j < NT; j++)
                    mma16816(acc[i][j], ra[cur][i][1], rb[cur][j][0]);
        }
        __syncthreads();
    }
    cp_wait<0>();

#pragma unroll
    for (int i = 0; i < MT; i++) {
        const int row = m0 + wm * 64 + i * 16 + (lane >> 2);
#pragma unroll
        for (int j = 0; j < NT; j++) {
            const int col = n0 + wn * (NT * 8) + j * 8 + ((lane & 3) << 1);
            float b0 = 0.f, b1 = 0.f;
            if (bias) { b0 = bias[col]; b1 = bias[col + 1]; }
#pragma unroll
            for (int hlf = 0; hlf < 2; hlf++) {
                const int r = row + hlf * 8;
                float v0 = acc[i][j][hlf * 2 + 0] * scale + b0;
                float v1 = acc[i][j][hlf * 2 + 1] * scale + b1;
                if (DOGELU) { v0 = gelu_exact(v0); v1 = gelu_exact(v1); }
                const size_t idx = (size_t)r * ldc + col;
                if (OUT == 0) {
                    if (resid) {
                        const float2 rr = *(const float2*)(resid + idx);
                        v0 += rr.x; v1 += rr.y;
                    }
                    float2 o; o.x = v0; o.y = v1;
                    *(float2*)(C + idx) = o;
                } else {
                    unsigned h, l;
                    split_pack2(v0, v1, h, l);
                    *(unsigned*)(Chi + idx) = h;
                    *(unsigned*)(Clo + idx) = l;
                }
            }
        }
    }
}

// ---------------------------------------------------------------------------
// Host orchestration
// ---------------------------------------------------------------------------
extern "C" void kernel_launch(void* const* d_in, const int* in_sizes, int n_in,
                              void* d_out, int out_size) {
    (void)in_sizes; (void)n_in; (void)out_size;
    const int*   ids   = (const int*)  d_in[0];
    const float* ctx   = (const float*)d_in[1];
    const float* tok   = (const float*)d_in[2];
    const float* pos   = (const float*)d_in[3];
    const float* qkvw  = (const float*)d_in[4];
    const float* qkvb  = (const float*)d_in[5];
    const float* projw = (const float*)d_in[6];
    const float* projb = (const float*)d_in[7];
    const float* ln1w  = (const float*)d_in[8];
    const float* ln1b  = (const float*)d_in[9];
    const float* ln2w  = (const float*)d_in[10];
    const float* ln2b  = (const float*)d_in[11];
    const float* f1w   = (const float*)d_in[12];
    const float* f1b   = (const float*)d_in[13];
    const float* f2w   = (const float*)d_in[14];
    const float* f2b   = (const float*)d_in[15];
    const float* lnfw  = (const float*)d_in[16];
    const float* lnfb  = (const float*)d_in[17];
    float* out = (float*)d_out;

    float *x;
    __nv_bfloat16 *hhi,*hlo,*qhi,*qlo,*ahi,*alo,*mhi,*mlo,*whi,*wlo;
    cudaGetSymbolAddress((void**)&x,   g_x);
    cudaGetSymbolAddress((void**)&hhi, g_h_hi);   cudaGetSymbolAddress((void**)&hlo, g_h_lo);
    cudaGetSymbolAddress((void**)&qhi, g_qkv_hi); cudaGetSymbolAddress((void**)&qlo, g_qkv_lo);
    cudaGetSymbolAddress((void**)&ahi, g_at_hi);  cudaGetSymbolAddress((void**)&alo, g_at_lo);
    cudaGetSymbolAddress((void**)&mhi, g_mid_hi); cudaGetSymbolAddress((void**)&mlo, g_mid_lo);
    cudaGetSymbolAddress((void**)&whi, g_w_hi);   cudaGetSymbolAddress((void**)&wlo, g_w_lo);

    auto kF32  = tgemm_k<128,128,0,false>;   // fp32 out (+resid)
    auto kSPL  = tgemm_k<128,128,1,false>;   // split planes out
    auto kSPLG = tgemm_k<128,128,1,true >;   // split planes out + GELU

    const int SM_NT = 3 * (2*128*128 + 2*128*128);   // 196608
    const int SM_FA = 3 * (4*128*128);               // 196608
    cudaFuncSetAttribute(kF32,    cudaFuncAttributeMaxDynamicSharedMemorySize, SM_NT);
    cudaFuncSetAttribute(kSPL,    cudaFuncAttributeMaxDynamicSharedMemorySize, SM_NT);
    cudaFuncSetAttribute(kSPLG,   cudaFuncAttributeMaxDynamicSharedMemorySize, SM_NT);
    cudaFuncSetAttribute(fattn_k, cudaFuncAttributeMaxDynamicSharedMemorySize, SM_FA);

    // ---- split all weights into bf16 hi/lo planes ----
    split_k<<<2048, 256>>>(qkvw,  whi + QW_OFF, wlo + QW_OFF, (long)(QW_SZ / 4));
    split_k<<<2048, 256>>>(projw, whi + PW_OFF, wlo + PW_OFF, (long)(PW_SZ / 4));
    split_k<<<2048, 256>>>(f1w,   whi + F1_OFF, wlo + F1_OFF, (long)(F1_SZ / 4));
    split_k<<<2048, 256>>>(f2w,   whi + F2_OFF, wlo + F2_OFF, (long)(F2_SZ / 4));
    split_k<<<2048, 256>>>(tok,   whi + TK_OFF, wlo + TK_OFF, (long)(TK_SZ / 4));

    const float attn_scale = 0.125f;   // 1/sqrt(64)

    embed_k<<<BTOK, 256>>>(ids, tok, pos, ctx, x);

    for (int l = 0; l < LAYERS; l++) {
        layernorm_split_k<<<BTOK, 256>>>(x, hhi, hlo,
                                         ln1w + (size_t)l*DM, ln1b + (size_t)l*DM);

        // qkv = h @ qkv_w^T + qkv_b  -> split planes
        kSPL<<<dim3(24, 32, 1), 256, SM_NT>>>(
            hhi, hlo, DM,
            whi + QW_OFF + (size_t)l*3*DM*DM, wlo + QW_OFF + (size_t)l*3*DM*DM, DM,
            nullptr, qhi, qlo, 3*DM,
            DM, qkvb + (size_t)l*3*DM, nullptr, 1.0f);

        // fused causal attention -> split planes
        fattn_k<<<dim3(TT/128, BBATCH*NH), 256, SM_FA>>>(
            qhi, qlo, ahi, alo, attn_scale);

        // x += attn @ proj_w^T + proj_b  (fp32 + residual)
        kF32<<<dim3(8, 32, 1), 256, SM_NT>>>(
            ahi, alo, DM,
            whi + PW_OFF + (size_t)l*DM*DM, wlo + PW_OFF + (size_t)l*DM*DM, DM,
            x, nullptr, nullptr, DM,
            DM, projb + (size_t)l*DM, x, 1.0f);

        layernorm_split_k<<<BTOK, 256>>>(x, hhi, hlo,
                                         ln2w + (size_t)l*DM, ln2b + (size_t)l*DM);

        // mid = gelu(h @ f1_w^T + f1_b) -> split planes
        kSPLG<<<dim3(32, 32, 1), 256, SM_NT>>>(
            hhi, hlo, DM,
            whi + F1_OFF + (size_t)l*4*DM*DM, wlo + F1_OFF + (size_t)l*4*DM*DM, DM,
            nullptr, mhi, mlo, 4*DM,
            DM, f1b + (size_t)l*4*DM, nullptr, 1.0f);

        // x += mid @ f2_w^T + f2_b  (fp32 + residual)
        kF32<<<dim3(8, 32, 1), 256, SM_NT>>>(
            mhi, mlo, 4*DM,
            whi + F2_OFF + (size_t)l*DM*4*DM, wlo + F2_OFF + (size_t)l*DM*4*DM, 4*DM,
            x, nullptr, nullptr, DM,
            4*DM, f2b + (size_t)l*DM, x, 1.0f);
    }

    layernorm_split_k<<<BTOK, 256>>>(x, hhi, hlo, lnfw, lnfb);

    // logits = h @ tok_emb^T (fp32)
    kF32<<<dim3(250, 32, 1), 256, SM_NT>>>(
        hhi, hlo, DM,
        whi + TK_OFF, wlo + TK_OFF, DM,
        out, nullptr, nullptr, VO,
        DM, nullptr, nullptr, 1.0f);
}